// round 15
// baseline (speedup 1.0000x reference)
#include <cuda_runtime.h>
#include <cuda_fp16.h>
#include <cstdint>
#include <math_constants.h>

// VectorQuantizer, barrier-free warp-autonomous, tuned for 2 CTAs/SM.
// R15 = R13 16px/warp structure with (a) __launch_bounds__(512,2) capping
// regs at 64 so TWO CTAs fit per SM (R13/R14 burned the whole register file
// at 1 CTA -> issue-starved at occ 18%), (b) n-blocking shrunk to 32 codes
// (acc 16 regs) to fit the budget. smem 104KB <= 113KB/CTA for 2 CTAs.
// fp16 1-pass + MARGIN 6e-5 validated rel_err=0.0 (R12-R14); exact fp32
// rescue bit-matched the reference (R1/R2).

#define VQ_K 512
#define VQ_D 64
#define VQ_HW 4096
#define NWTILES 8192         // 131072 px / 16 px per warp-tile
#define THREADS 512
#define NWARPS 16
#define GRID 304
#define MARGIN 6e-5f

// ---- shared memory layout (bytes) ----
#define SM_B0   0                       // codebook fp16 [512][128B]  64 KB
#define SM_ESQ  65536                   // f32 e_sq[512]               2 KB
#define SM_A    67584                   // per-warp A slices: 16 x 2048 = 32 KB
#define SM_SCR  100352                  // per-warp scratch: 16 x 384
#define SMEM_TOTAL 106496
// scratch per warp: f32 xrow[64] (256B) + int win[16] (64B) + pad

__device__ __forceinline__ int swz(int row, int chunk) {
    return row * 128 + ((chunk ^ (row & 7)) << 4);
}
__device__ __forceinline__ uint32_t sptr(const void* p) {
    return (uint32_t)__cvta_generic_to_shared(p);
}
#define LDSM4(r0, r1, r2, r3, addr)                                            \
    asm volatile("ldmatrix.sync.aligned.m8n8.x4.shared.b16 {%0,%1,%2,%3}, [%4];" \
                 : "=r"(r0), "=r"(r1), "=r"(r2), "=r"(r3) : "r"(addr))

__device__ __forceinline__ void hmma(float& d0, float& d1, float& d2, float& d3,
                                     uint32_t a0, uint32_t a1, uint32_t a2, uint32_t a3,
                                     uint32_t b0, uint32_t b1) {
    asm volatile(
        "mma.sync.aligned.m16n8k16.row.col.f32.f16.f16.f32 "
        "{%0,%1,%2,%3}, {%4,%5,%6,%7}, {%8,%9}, {%0,%1,%2,%3};"
        : "+f"(d0), "+f"(d1), "+f"(d2), "+f"(d3)
        : "r"(a0), "r"(a1), "r"(a2), "r"(a3), "r"(b0), "r"(b1));
}

__device__ __forceinline__ uint32_t pack2h(float a, float b) {
    __half2 h = __floats2half2_rn(a, b);
    return *reinterpret_cast<uint32_t*>(&h);
}

// Exact fp32 distance, numerics identical to round-1 (bit-matched reference):
// sequential FMA dot over channels, dist = fl(fl(xsq+esq) + (-2*dot)).
__device__ __forceinline__ float exact_dist(const float* __restrict__ xrow,
                                            const float* __restrict__ emb,
                                            float xsq, float esqk, int k) {
    const float4* er = reinterpret_cast<const float4*>(emb + (size_t)k * VQ_D);
    float dot = 0.0f;
    #pragma unroll
    for (int q = 0; q < 16; q++) {
        const float4 f = __ldg(er + q);
        dot = __fmaf_rn(xrow[4 * q + 0], f.x, dot);
        dot = __fmaf_rn(xrow[4 * q + 1], f.y, dot);
        dot = __fmaf_rn(xrow[4 * q + 2], f.z, dot);
        dot = __fmaf_rn(xrow[4 * q + 3], f.w, dot);
    }
    return __fadd_rn(__fadd_rn(xsq, esqk), __fmul_rn(-2.0f, dot));
}

__global__ __launch_bounds__(THREADS, 2)
void vq_hmma_kernel(const float* __restrict__ x,
                    const float* __restrict__ emb,
                    float* __restrict__ out) {
    extern __shared__ char sm[];
    float* esq = reinterpret_cast<float*>(sm + SM_ESQ);

    const int tid  = threadIdx.x;
    const int wid  = tid >> 5;
    const int lane = tid & 31;
    const int g    = lane & 3;
    const int qr   = lane >> 2;

    char*  aslice = sm + SM_A + wid * 2048;
    float* scrX   = reinterpret_cast<float*>(sm + SM_SCR + wid * 384);
    int*   scrWin = reinterpret_cast<int*>(sm + SM_SCR + wid * 384 + 256);

    // ---- prologue: stage codebook fp16 (swizzled) + exact e_sq ----
    #pragma unroll 4
    for (int it = 0; it < 16; it++) {
        const int lin = it * THREADS + tid;          // 8192 float4s
        const int k = lin >> 4, q = lin & 15;
        const float4 f = __ldg(reinterpret_cast<const float4*>(emb + k * VQ_D) + q);
        const int off = swz(k, q >> 1) + (q & 1) * 8;
        *reinterpret_cast<uint2*>(sm + SM_B0 + off) =
            make_uint2(pack2h(f.x, f.y), pack2h(f.z, f.w));
    }
    {
        const int k = tid;                           // THREADS == VQ_K
        const float4* er = reinterpret_cast<const float4*>(emb + k * VQ_D);
        float s = 0.0f;
        #pragma unroll
        for (int q = 0; q < 16; q++) {
            const float4 f = __ldg(er + q);
            s = __fadd_rn(s, __fmul_rn(f.x, f.x));
            s = __fadd_rn(s, __fmul_rn(f.y, f.y));
            s = __fadd_rn(s, __fmul_rn(f.z, f.z));
            s = __fadd_rn(s, __fmul_rn(f.w, f.w));
        }
        esq[k] = s;
    }
    __syncthreads();   // only block barrier in the kernel

    const int browo = (lane & 7) + (lane >> 4) * 8;
    const int bchs  = (lane >> 3) & 1;
    const int arowL = (lane & 7) + ((lane >> 3) & 1) * 8;

    // warp-major tile interleave spreads the 1-vs-2-tile tail across SMs
    for (int wt = wid * GRID + blockIdx.x; wt < NWTILES; wt += GRID * NWARPS) {
        const int p0 = wt * 16;
        const int b  = p0 >> 12;
        const int hw = p0 & 4095;
        const float* xb = x + (size_t)b * VQ_D * VQ_HW + hw;
        float* ob = out + (size_t)b * VQ_D * VQ_HW + hw;

        __syncwarp();   // previous tile's LDSM fully done before slice rewrite

        // ---- stage this warp's 16 x-rows into its fp16 A slice ----
        #pragma unroll
        for (int h = 0; h < 8; h++) {
            uint32_t pr[4];
            #pragma unroll
            for (int jj = 0; jj < 4; jj++) {
                const int j = 4 * h + jj;
                const int c = 2 * j + (lane >> 4);
                const int p = lane & 15;
                const float v = __ldg(xb + (size_t)c * VQ_HW + p);
                const float o = __shfl_xor_sync(0xffffffffu, v, 16);
                pr[jj] = pack2h(v, o);               // valid on lanes < 16
            }
            if (lane < 16) {
                *reinterpret_cast<uint4*>(aslice + swz(lane, h)) =
                    make_uint4(pr[0], pr[1], pr[2], pr[3]);
            }
        }
        __syncwarp();

        // ---- A fragments via ldmatrix.x4 ----
        uint32_t aF[4][4];
        #pragma unroll
        for (int ks = 0; ks < 4; ks++) {
            const int ach = 2 * ks + (lane >> 4);
            LDSM4(aF[ks][0], aF[ks][1], aF[ks][2], aF[ks][3],
                  sptr(aslice + swz(arowL, ach)));
        }

        // ---- m16 x n512 x k64: branchless top-2 per row (r0, r1) ----
        float m1[2] = {CUDART_INF_F, CUDART_INF_F};
        float m2[2] = {CUDART_INF_F, CUDART_INF_F};
        int   ki[2] = {0x7FFFFFFF, 0x7FFFFFFF};

        #define UPD(rr, s, kk) {                                   \
            const bool lt = (s) < m1[rr];                          \
            m2[rr] = fminf(m2[rr], lt ? m1[rr] : (s));             \
            ki[rr] = lt ? (kk) : ki[rr];                           \
            m1[rr] = lt ? (s) : m1[rr]; }

        for (int nc = 0; nc < 16; nc++) {     // 16 chunks of 32 codes
            float acc[4][4];
            #pragma unroll
            for (int nf = 0; nf < 4; nf++) {
                acc[nf][0] = 0.f; acc[nf][1] = 0.f; acc[nf][2] = 0.f; acc[nf][3] = 0.f;
            }
            #pragma unroll
            for (int ks = 0; ks < 4; ks++) {
                uint32_t bh[4][2];
                #pragma unroll
                for (int pr2 = 0; pr2 < 2; pr2++) {
                    const int row = nc * 32 + pr2 * 16 + browo;
                    const int ch  = 2 * ks + bchs;
                    LDSM4(bh[2 * pr2][0], bh[2 * pr2][1],
                          bh[2 * pr2 + 1][0], bh[2 * pr2 + 1][1],
                          sptr(sm + SM_B0 + swz(row, ch)));
                }
                #pragma unroll
                for (int nf = 0; nf < 4; nf++)
                    hmma(acc[nf][0], acc[nf][1], acc[nf][2], acc[nf][3],
                         aF[ks][0], aF[ks][1], aF[ks][2], aF[ks][3],
                         bh[nf][0], bh[nf][1]);
            }
            #pragma unroll
            for (int nf = 0; nf < 4; nf++) {
                const int col = nc * 32 + nf * 8 + 2 * g;
                const float2 eq = *reinterpret_cast<const float2*>(esq + col);
                float s;
                s = __fmaf_rn(-2.0f, acc[nf][0], eq.x); UPD(0, s, col);
                s = __fmaf_rn(-2.0f, acc[nf][1], eq.y); UPD(0, s, col + 1);
                s = __fmaf_rn(-2.0f, acc[nf][2], eq.x); UPD(1, s, col);
                s = __fmaf_rn(-2.0f, acc[nf][3], eq.y); UPD(1, s, col + 1);
            }
        }
        #undef UPD

        // ---- quad reduce (converged, full warp); winner or -1 ----
        #pragma unroll
        for (int rr = 0; rr < 2; rr++) {
            #pragma unroll
            for (int d = 1; d <= 2; d <<= 1) {
                const float o1 = __shfl_xor_sync(0xffffffffu, m1[rr], d);
                const float o2 = __shfl_xor_sync(0xffffffffu, m2[rr], d);
                const int   oi = __shfl_xor_sync(0xffffffffu, ki[rr], d);
                const bool take = (o1 < m1[rr]) || (o1 == m1[rr] && oi < ki[rr]);
                m2[rr] = fminf(fminf(m2[rr], o2), take ? m1[rr] : o1);
                ki[rr] = take ? oi : ki[rr];
                m1[rr] = take ? o1 : m1[rr];
            }
            if (g == 0) {
                const int row = qr + 8 * rr;
                scrWin[row] = (m2[rr] - m1[rr] > MARGIN) ? ki[rr] : -1;
            }
        }
        __syncwarp();

        // ---- in-warp exact rescue (warp-uniform control flow) ----
        #pragma unroll 1
        for (int r = 0; r < 16; r++) {
            if (scrWin[r] != -1) continue;          // LDS broadcast, uniform
            scrX[lane]      = __ldg(xb + (size_t)lane * VQ_HW + r);
            scrX[lane + 32] = __ldg(xb + (size_t)(lane + 32) * VQ_HW + r);
            __syncwarp();
            float xq = 0.0f;
            #pragma unroll
            for (int c = 0; c < VQ_D; c++)
                xq = __fadd_rn(xq, __fmul_rn(scrX[c], scrX[c]));
            float bd = CUDART_INF_F; int bk = 0x7FFFFFFF;
            #pragma unroll 2
            for (int k = lane; k < VQ_K; k += 32) {
                const float d = exact_dist(scrX, emb, xq, esq[k], k);
                if (d < bd || (d == bd && k < bk)) { bd = d; bk = k; }
            }
            #pragma unroll
            for (int off = 16; off; off >>= 1) {
                const float od = __shfl_xor_sync(0xffffffffu, bd, off);
                const int   oi = __shfl_xor_sync(0xffffffffu, bk, off);
                if (od < bd || (od == bd && oi < bk)) { bd = od; bk = oi; }
            }
            if (lane == 0) scrWin[r] = bk;
            __syncwarp();
        }
        __syncwarp();

        // ---- gather winners + store (float4 along pixel dim) ----
        #pragma unroll
        for (int it = 0; it < 8; it++) {
            const int c  = it * 8 + (lane >> 2);
            const int p4 = (lane & 3) * 4;
            const int w0 = scrWin[p4 + 0], w1 = scrWin[p4 + 1];
            const int w2 = scrWin[p4 + 2], w3 = scrWin[p4 + 3];
            float4 v;
            v.x = __ldg(emb + (size_t)w0 * VQ_D + c);
            v.y = __ldg(emb + (size_t)w1 * VQ_D + c);
            v.z = __ldg(emb + (size_t)w2 * VQ_D + c);
            v.w = __ldg(emb + (size_t)w3 * VQ_D + c);
            *reinterpret_cast<float4*>(ob + (size_t)c * VQ_HW + p4) = v;
        }
    }
}

extern "C" void kernel_launch(void* const* d_in, const int* in_sizes, int n_in,
                              void* d_out, int out_size) {
    (void)in_sizes; (void)n_in; (void)out_size;
    const float* x   = (const float*)d_in[0];
    const float* emb = (const float*)d_in[1];
    float* out = (float*)d_out;

    cudaFuncSetAttribute(vq_hmma_kernel, cudaFuncAttributeMaxDynamicSharedMemorySize,
                         SMEM_TOTAL);

    vq_hmma_kernel<<<GRID, THREADS, SMEM_TOTAL>>>(x, emb, out);
}

// round 16
// speedup vs baseline: 1.1259x; 1.1259x over previous
#include <cuda_runtime.h>
#include <cuda_fp16.h>
#include <cstdint>
#include <math_constants.h>

// VectorQuantizer, barrier-free warp-autonomous, 32 px/warp (R14 base, 122.9us).
// R16: (a) staging rewritten shuffle-free: 32 independent scalar LDGs per lane
// (MLP ~32) then pack+STS.128 -- removes the per-element LDG->SHFL serial chain;
// (b) top-2 tracking on index-embedded keys (low 9 mantissa bits := code index,
// one LOP3/score) reduced with pure FMNMX pairing (5 inst/score, no FSETP/SEL).
// Key quantization perturbs scores <= ~1e-5; MARGIN raised to 1e-4. Quantized
// ties land inside the margin -> exact rescue, so tie order never decides
// output. fp16 1-pass GEMM + exact fp32 rescue validated rel_err=0.0 (R12-R15).

#define VQ_K 512
#define VQ_D 64
#define VQ_HW 4096
#define NWTILES 4096         // 131072 px / 32 px per warp-tile
#define THREADS 512
#define NWARPS 16
#define GRID 152
#define MARGIN 1e-4f

// ---- shared memory layout (bytes) ----
#define SM_B0   0                       // codebook fp16 [512][128B]  64 KB
#define SM_ESQ  65536                   // f32 e_sq[512]               2 KB
#define SM_A    67584                   // per-warp A slices: 16 x 4096 = 64 KB
#define SM_SCR  133120                  // per-warp scratch: 16 x 512
#define SMEM_TOTAL 141312
// scratch per warp: f32 xrow[64] (256B) + int win[32] (128B) + pad

__device__ __forceinline__ int swz(int row, int chunk) {
    return row * 128 + ((chunk ^ (row & 7)) << 4);
}
__device__ __forceinline__ uint32_t sptr(const void* p) {
    return (uint32_t)__cvta_generic_to_shared(p);
}
#define LDSM4(r0, r1, r2, r3, addr)                                            \
    asm volatile("ldmatrix.sync.aligned.m8n8.x4.shared.b16 {%0,%1,%2,%3}, [%4];" \
                 : "=r"(r0), "=r"(r1), "=r"(r2), "=r"(r3) : "r"(addr))

__device__ __forceinline__ void hmma(float& d0, float& d1, float& d2, float& d3,
                                     uint32_t a0, uint32_t a1, uint32_t a2, uint32_t a3,
                                     uint32_t b0, uint32_t b1) {
    asm volatile(
        "mma.sync.aligned.m16n8k16.row.col.f32.f16.f16.f32 "
        "{%0,%1,%2,%3}, {%4,%5,%6,%7}, {%8,%9}, {%0,%1,%2,%3};"
        : "+f"(d0), "+f"(d1), "+f"(d2), "+f"(d3)
        : "r"(a0), "r"(a1), "r"(a2), "r"(a3), "r"(b0), "r"(b1));
}

__device__ __forceinline__ uint32_t pack2h(float a, float b) {
    __half2 h = __floats2half2_rn(a, b);
    return *reinterpret_cast<uint32_t*>(&h);
}

// score -> sortable key with code index in the low 9 mantissa bits.
__device__ __forceinline__ float mkkey(float s, int col) {
    return __int_as_float((__float_as_int(s) & 0xFFFFFE00) | col);
}

// Exact fp32 distance, numerics identical to round-1 (bit-matched reference):
// sequential FMA dot over channels, dist = fl(fl(xsq+esq) + (-2*dot)).
__device__ __forceinline__ float exact_dist(const float* __restrict__ xrow,
                                            const float* __restrict__ emb,
                                            float xsq, float esqk, int k) {
    const float4* er = reinterpret_cast<const float4*>(emb + (size_t)k * VQ_D);
    float dot = 0.0f;
    #pragma unroll
    for (int q = 0; q < 16; q++) {
        const float4 f = __ldg(er + q);
        dot = __fmaf_rn(xrow[4 * q + 0], f.x, dot);
        dot = __fmaf_rn(xrow[4 * q + 1], f.y, dot);
        dot = __fmaf_rn(xrow[4 * q + 2], f.z, dot);
        dot = __fmaf_rn(xrow[4 * q + 3], f.w, dot);
    }
    return __fadd_rn(__fadd_rn(xsq, esqk), __fmul_rn(-2.0f, dot));
}

__global__ __launch_bounds__(THREADS, 1)
void vq_hmma_kernel(const float* __restrict__ x,
                    const float* __restrict__ emb,
                    float* __restrict__ out) {
    extern __shared__ char sm[];
    float* esq = reinterpret_cast<float*>(sm + SM_ESQ);

    const int tid  = threadIdx.x;
    const int wid  = tid >> 5;
    const int lane = tid & 31;
    const int g    = lane & 3;
    const int qr   = lane >> 2;

    char*  aslice = sm + SM_A + wid * 4096;          // 2 tiles x 2048B
    float* scrX   = reinterpret_cast<float*>(sm + SM_SCR + wid * 512);
    int*   scrWin = reinterpret_cast<int*>(sm + SM_SCR + wid * 512 + 256);

    // ---- prologue: stage codebook fp16 (swizzled) + exact e_sq ----
    #pragma unroll 4
    for (int it = 0; it < 16; it++) {
        const int lin = it * THREADS + tid;          // 8192 float4s
        const int k = lin >> 4, q = lin & 15;
        const float4 f = __ldg(reinterpret_cast<const float4*>(emb + k * VQ_D) + q);
        const int off = swz(k, q >> 1) + (q & 1) * 8;
        *reinterpret_cast<uint2*>(sm + SM_B0 + off) =
            make_uint2(pack2h(f.x, f.y), pack2h(f.z, f.w));
    }
    {
        const int k = tid;                           // THREADS == VQ_K
        const float4* er = reinterpret_cast<const float4*>(emb + k * VQ_D);
        float s = 0.0f;
        #pragma unroll
        for (int q = 0; q < 16; q++) {
            const float4 f = __ldg(er + q);
            s = __fadd_rn(s, __fmul_rn(f.x, f.x));
            s = __fadd_rn(s, __fmul_rn(f.y, f.y));
            s = __fadd_rn(s, __fmul_rn(f.z, f.z));
            s = __fadd_rn(s, __fmul_rn(f.w, f.w));
        }
        esq[k] = s;
    }
    __syncthreads();   // only block barrier in the kernel

    const int browo = (lane & 7) + (lane >> 4) * 8;
    const int bchs  = (lane >> 3) & 1;
    const int arowL = (lane & 7) + ((lane >> 3) & 1) * 8;
    const int prow  = lane & 15;          // staging: pixel row this lane owns
    const int hbase = (lane >> 4) * 4;    // staging: chunk half this lane owns

    // warp-major tile interleave balances the tail across SMs
    for (int wt = wid * GRID + blockIdx.x; wt < NWTILES; wt += GRID * NWARPS) {
        const int p0 = wt * 32;
        const int b  = p0 >> 12;
        const int hw = p0 & 4095;
        const float* xb = x + (size_t)b * VQ_D * VQ_HW + hw;
        float* ob = out + (size_t)b * VQ_D * VQ_HW + hw;

        __syncwarp();   // previous tile's LDSM fully done before slice rewrite

        // ---- stage 32 x-rows into two fp16 A tiles (shuffle-free, MLP~32) ----
        #pragma unroll
        for (int t = 0; t < 2; t++) {
            const float* xt = xb + 16 * t;
            char* at = aslice + 2048 * t;
            float v[4][8];
            #pragma unroll
            for (int hh = 0; hh < 4; hh++)
                #pragma unroll
                for (int j = 0; j < 8; j++)
                    v[hh][j] = __ldg(xt + (size_t)((hbase + hh) * 8 + j) * VQ_HW + prow);
            #pragma unroll
            for (int hh = 0; hh < 4; hh++) {
                *reinterpret_cast<uint4*>(at + swz(prow, hbase + hh)) =
                    make_uint4(pack2h(v[hh][0], v[hh][1]), pack2h(v[hh][2], v[hh][3]),
                               pack2h(v[hh][4], v[hh][5]), pack2h(v[hh][6], v[hh][7]));
            }
        }
        __syncwarp();

        // ---- A fragments via ldmatrix.x4 (both tiles) ----
        uint32_t aF[2][4][4];
        #pragma unroll
        for (int t = 0; t < 2; t++) {
            #pragma unroll
            for (int ks = 0; ks < 4; ks++) {
                const int ach = 2 * ks + (lane >> 4);
                LDSM4(aF[t][ks][0], aF[t][ks][1], aF[t][ks][2], aF[t][ks][3],
                      sptr(aslice + 2048 * t + swz(arowL, ach)));
            }
        }

        // ---- m32 x n512 x k64: keyed top-2, 4 rows per thread ----
        float m1[4] = {CUDART_INF_F, CUDART_INF_F, CUDART_INF_F, CUDART_INF_F};
        float m2[4] = {CUDART_INF_F, CUDART_INF_F, CUDART_INF_F, CUDART_INF_F};

        // merge a (lo,hi)-pair of keys into row rr's top-2 (pure FMNMX)
        #define MERGE(rr, k0, k1) {                               \
            const float lo = fminf(k0, k1);                       \
            const float hi = fmaxf(k0, k1);                       \
            const float tx = fmaxf(m1[rr], lo);                   \
            m2[rr] = fminf(fminf(m2[rr], tx), hi);                \
            m1[rr] = fminf(m1[rr], lo); }

        for (int nc = 0; nc < 8; nc++) {          // 8 chunks of 64 codes
            #pragma unroll
            for (int h = 0; h < 2; h++) {         // n-half: nf in [4h, 4h+4)
                float acc[2][4][4];
                #pragma unroll
                for (int t = 0; t < 2; t++)
                    #pragma unroll
                    for (int nfl = 0; nfl < 4; nfl++) {
                        acc[t][nfl][0] = 0.f; acc[t][nfl][1] = 0.f;
                        acc[t][nfl][2] = 0.f; acc[t][nfl][3] = 0.f;
                    }
                #pragma unroll
                for (int ks = 0; ks < 4; ks++) {
                    uint32_t bh[4][2];
                    #pragma unroll
                    for (int pr2 = 0; pr2 < 2; pr2++) {
                        const int row = nc * 64 + (2 * h + pr2) * 16 + browo;
                        const int ch  = 2 * ks + bchs;
                        LDSM4(bh[2 * pr2][0], bh[2 * pr2][1],
                              bh[2 * pr2 + 1][0], bh[2 * pr2 + 1][1],
                              sptr(sm + SM_B0 + swz(row, ch)));
                    }
                    #pragma unroll
                    for (int t = 0; t < 2; t++)
                        #pragma unroll
                        for (int nfl = 0; nfl < 4; nfl++)
                            hmma(acc[t][nfl][0], acc[t][nfl][1],
                                 acc[t][nfl][2], acc[t][nfl][3],
                                 aF[t][ks][0], aF[t][ks][1],
                                 aF[t][ks][2], aF[t][ks][3],
                                 bh[nfl][0], bh[nfl][1]);
                }
                // scores: rank = esq - 2*dot; keys embed the code index
                #pragma unroll
                for (int t = 0; t < 2; t++)
                    #pragma unroll
                    for (int nfl = 0; nfl < 4; nfl++) {
                        const int col = nc * 64 + (4 * h + nfl) * 8 + 2 * g;
                        const float2 eq = *reinterpret_cast<const float2*>(esq + col);
                        const float k0 = mkkey(__fmaf_rn(-2.0f, acc[t][nfl][0], eq.x), col);
                        const float k1 = mkkey(__fmaf_rn(-2.0f, acc[t][nfl][1], eq.y), col + 1);
                        MERGE(2 * t + 0, k0, k1);
                        const float k2 = mkkey(__fmaf_rn(-2.0f, acc[t][nfl][2], eq.x), col);
                        const float k3 = mkkey(__fmaf_rn(-2.0f, acc[t][nfl][3], eq.y), col + 1);
                        MERGE(2 * t + 1, k2, k3);
                    }
            }
        }
        #undef MERGE

        // ---- quad reduce on keys (pure FMNMX + shuffles); winner or -1 ----
        #pragma unroll
        for (int rr = 0; rr < 4; rr++) {
            #pragma unroll
            for (int d = 1; d <= 2; d <<= 1) {
                const float o1 = __shfl_xor_sync(0xffffffffu, m1[rr], d);
                const float o2 = __shfl_xor_sync(0xffffffffu, m2[rr], d);
                const float tx = fmaxf(m1[rr], o1);
                m2[rr] = fminf(fminf(m2[rr], o2), tx);
                m1[rr] = fminf(m1[rr], o1);
            }
            if (g == 0) {
                const int row = (rr >> 1) * 16 + qr + 8 * (rr & 1);
                scrWin[row] = (m2[rr] - m1[rr] > MARGIN)
                              ? (__float_as_int(m1[rr]) & 0x1FF) : -1;
            }
        }
        __syncwarp();

        // ---- in-warp exact rescue (warp-uniform control flow) ----
        #pragma unroll 1
        for (int r = 0; r < 32; r++) {
            if (scrWin[r] != -1) continue;          // LDS broadcast, uniform
            scrX[lane]      = __ldg(xb + (size_t)lane * VQ_HW + r);
            scrX[lane + 32] = __ldg(xb + (size_t)(lane + 32) * VQ_HW + r);
            __syncwarp();
            float xq = 0.0f;
            #pragma unroll
            for (int c = 0; c < VQ_D; c++)
                xq = __fadd_rn(xq, __fmul_rn(scrX[c], scrX[c]));
            float bd = CUDART_INF_F; int bk = 0x7FFFFFFF;
            #pragma unroll 2
            for (int k = lane; k < VQ_K; k += 32) {
                const float d = exact_dist(scrX, emb, xq, esq[k], k);
                if (d < bd || (d == bd && k < bk)) { bd = d; bk = k; }
            }
            #pragma unroll
            for (int off = 16; off; off >>= 1) {
                const float od = __shfl_xor_sync(0xffffffffu, bd, off);
                const int   oi = __shfl_xor_sync(0xffffffffu, bk, off);
                if (od < bd || (od == bd && oi < bk)) { bd = od; bk = oi; }
            }
            if (lane == 0) scrWin[r] = bk;
            __syncwarp();
        }
        __syncwarp();

        // ---- gather winners + store (float4 along pixel dim), both halves ----
        #pragma unroll
        for (int t = 0; t < 2; t++) {
            #pragma unroll
            for (int it = 0; it < 8; it++) {
                const int c  = it * 8 + (lane >> 2);
                const int p4 = (lane & 3) * 4;
                const int w0 = scrWin[16 * t + p4 + 0], w1 = scrWin[16 * t + p4 + 1];
                const int w2 = scrWin[16 * t + p4 + 2], w3 = scrWin[16 * t + p4 + 3];
                float4 v;
                v.x = __ldg(emb + (size_t)w0 * VQ_D + c);
                v.y = __ldg(emb + (size_t)w1 * VQ_D + c);
                v.z = __ldg(emb + (size_t)w2 * VQ_D + c);
                v.w = __ldg(emb + (size_t)w3 * VQ_D + c);
                *reinterpret_cast<float4*>(ob + (size_t)c * VQ_HW + 16 * t + p4) = v;
            }
        }
    }
}

extern "C" void kernel_launch(void* const* d_in, const int* in_sizes, int n_in,
                              void* d_out, int out_size) {
    (void)in_sizes; (void)n_in; (void)out_size;
    const float* x   = (const float*)d_in[0];
    const float* emb = (const float*)d_in[1];
    float* out = (float*)d_out;

    cudaFuncSetAttribute(vq_hmma_kernel, cudaFuncAttributeMaxDynamicSharedMemorySize,
                         SMEM_TOTAL);

    vq_hmma_kernel<<<GRID, THREADS, SMEM_TOTAL>>>(x, emb, out);
}

// round 17
// speedup vs baseline: 1.1291x; 1.0029x over previous
#include <cuda_runtime.h>
#include <cuda_fp16.h>
#include <cstdint>
#include <math_constants.h>

// VectorQuantizer, barrier-free warp-autonomous, 32 px/warp.
// R17 = R14 (122.9us best, rel_err 0) with EXACTLY ONE change: score top-2
// tracking switched to index-embedded keys (low 9 mantissa bits := code index)
// reduced with pure FMNMX pair-merges (no FSETP/SEL chains), eq hoisted out of
// the t loop. Staging is R14's original (R16's prefetch-buffer staging caused
// the regression via register spills). Key-order artifacts on ties/negatives
// always fall inside MARGIN -> exact rescue (validated rel_err=0 in R16).
// fp16 1-pass GEMM + exact fp32 rescue validated rel_err=0.0 (R12-R16).

#define VQ_K 512
#define VQ_D 64
#define VQ_HW 4096
#define NWTILES 4096         // 131072 px / 32 px per warp-tile
#define THREADS 512
#define NWARPS 16
#define GRID 152
#define MARGIN 1e-4f

// ---- shared memory layout (bytes) ----
#define SM_B0   0                       // codebook fp16 [512][128B]  64 KB
#define SM_ESQ  65536                   // f32 e_sq[512]               2 KB
#define SM_A    67584                   // per-warp A slices: 16 x 4096 = 64 KB
#define SM_SCR  133120                  // per-warp scratch: 16 x 512
#define SMEM_TOTAL 141312
// scratch per warp: f32 xrow[64] (256B) + int win[32] (128B) + pad

__device__ __forceinline__ int swz(int row, int chunk) {
    return row * 128 + ((chunk ^ (row & 7)) << 4);
}
__device__ __forceinline__ uint32_t sptr(const void* p) {
    return (uint32_t)__cvta_generic_to_shared(p);
}
#define LDSM4(r0, r1, r2, r3, addr)                                            \
    asm volatile("ldmatrix.sync.aligned.m8n8.x4.shared.b16 {%0,%1,%2,%3}, [%4];" \
                 : "=r"(r0), "=r"(r1), "=r"(r2), "=r"(r3) : "r"(addr))

__device__ __forceinline__ void hmma(float& d0, float& d1, float& d2, float& d3,
                                     uint32_t a0, uint32_t a1, uint32_t a2, uint32_t a3,
                                     uint32_t b0, uint32_t b1) {
    asm volatile(
        "mma.sync.aligned.m16n8k16.row.col.f32.f16.f16.f32 "
        "{%0,%1,%2,%3}, {%4,%5,%6,%7}, {%8,%9}, {%0,%1,%2,%3};"
        : "+f"(d0), "+f"(d1), "+f"(d2), "+f"(d3)
        : "r"(a0), "r"(a1), "r"(a2), "r"(a3), "r"(b0), "r"(b1));
}

__device__ __forceinline__ uint32_t pack2h(float a, float b) {
    __half2 h = __floats2half2_rn(a, b);
    return *reinterpret_cast<uint32_t*>(&h);
}

// score -> sortable key with the code index in the low 9 mantissa bits.
__device__ __forceinline__ float mkkey(float s, int col) {
    return __int_as_float((__float_as_int(s) & 0xFFFFFE00) | col);
}

// Exact fp32 distance, numerics identical to round-1 (bit-matched reference):
// sequential FMA dot over channels, dist = fl(fl(xsq+esq) + (-2*dot)).
__device__ __forceinline__ float exact_dist(const float* __restrict__ xrow,
                                            const float* __restrict__ emb,
                                            float xsq, float esqk, int k) {
    const float4* er = reinterpret_cast<const float4*>(emb + (size_t)k * VQ_D);
    float dot = 0.0f;
    #pragma unroll
    for (int q = 0; q < 16; q++) {
        const float4 f = __ldg(er + q);
        dot = __fmaf_rn(xrow[4 * q + 0], f.x, dot);
        dot = __fmaf_rn(xrow[4 * q + 1], f.y, dot);
        dot = __fmaf_rn(xrow[4 * q + 2], f.z, dot);
        dot = __fmaf_rn(xrow[4 * q + 3], f.w, dot);
    }
    return __fadd_rn(__fadd_rn(xsq, esqk), __fmul_rn(-2.0f, dot));
}

__global__ __launch_bounds__(THREADS, 1)
void vq_hmma_kernel(const float* __restrict__ x,
                    const float* __restrict__ emb,
                    float* __restrict__ out) {
    extern __shared__ char sm[];
    float* esq = reinterpret_cast<float*>(sm + SM_ESQ);

    const int tid  = threadIdx.x;
    const int wid  = tid >> 5;
    const int lane = tid & 31;
    const int g    = lane & 3;
    const int qr   = lane >> 2;

    char*  aslice = sm + SM_A + wid * 4096;          // 2 tiles x 2048B
    float* scrX   = reinterpret_cast<float*>(sm + SM_SCR + wid * 512);
    int*   scrWin = reinterpret_cast<int*>(sm + SM_SCR + wid * 512 + 256);

    // ---- prologue: stage codebook fp16 (swizzled) + exact e_sq ----
    #pragma unroll 4
    for (int it = 0; it < 16; it++) {
        const int lin = it * THREADS + tid;          // 8192 float4s
        const int k = lin >> 4, q = lin & 15;
        const float4 f = __ldg(reinterpret_cast<const float4*>(emb + k * VQ_D) + q);
        const int off = swz(k, q >> 1) + (q & 1) * 8;
        *reinterpret_cast<uint2*>(sm + SM_B0 + off) =
            make_uint2(pack2h(f.x, f.y), pack2h(f.z, f.w));
    }
    {
        const int k = tid;                           // THREADS == VQ_K
        const float4* er = reinterpret_cast<const float4*>(emb + k * VQ_D);
        float s = 0.0f;
        #pragma unroll
        for (int q = 0; q < 16; q++) {
            const float4 f = __ldg(er + q);
            s = __fadd_rn(s, __fmul_rn(f.x, f.x));
            s = __fadd_rn(s, __fmul_rn(f.y, f.y));
            s = __fadd_rn(s, __fmul_rn(f.z, f.z));
            s = __fadd_rn(s, __fmul_rn(f.w, f.w));
        }
        esq[k] = s;
    }
    __syncthreads();   // only block barrier in the kernel

    const int browo = (lane & 7) + (lane >> 4) * 8;
    const int bchs  = (lane >> 3) & 1;
    const int arowL = (lane & 7) + ((lane >> 3) & 1) * 8;

    // warp-major tile interleave: balances 1-vs-2-tile warps across all SMs
    for (int wt = wid * GRID + blockIdx.x; wt < NWTILES; wt += GRID * NWARPS) {
        const int p0 = wt * 32;
        const int b  = p0 >> 12;
        const int hw = p0 & 4095;
        const float* xb = x + (size_t)b * VQ_D * VQ_HW + hw;
        float* ob = out + (size_t)b * VQ_D * VQ_HW + hw;

        __syncwarp();   // previous tile's LDSM fully done before slice rewrite

        // ---- stage 32 x-rows into two fp16 A tiles (R14 original) ----
        #pragma unroll
        for (int t = 0; t < 2; t++) {
            const float* xt = xb + 16 * t;
            char* at = aslice + 2048 * t;
            #pragma unroll
            for (int h = 0; h < 8; h++) {
                uint32_t pr[4];
                #pragma unroll
                for (int jj = 0; jj < 4; jj++) {
                    const int j = 4 * h + jj;
                    const int c = 2 * j + (lane >> 4);
                    const int p = lane & 15;
                    const float v = __ldg(xt + (size_t)c * VQ_HW + p);
                    const float o = __shfl_xor_sync(0xffffffffu, v, 16);
                    pr[jj] = pack2h(v, o);           // valid on lanes < 16
                }
                if (lane < 16) {
                    *reinterpret_cast<uint4*>(at + swz(lane, h)) =
                        make_uint4(pr[0], pr[1], pr[2], pr[3]);
                }
            }
        }
        __syncwarp();

        // ---- A fragments via ldmatrix.x4 (both tiles) ----
        uint32_t aF[2][4][4];
        #pragma unroll
        for (int t = 0; t < 2; t++) {
            #pragma unroll
            for (int ks = 0; ks < 4; ks++) {
                const int ach = 2 * ks + (lane >> 4);
                LDSM4(aF[t][ks][0], aF[t][ks][1], aF[t][ks][2], aF[t][ks][3],
                      sptr(aslice + 2048 * t + swz(arowL, ach)));
            }
        }

        // ---- m32 x n512 x k64: keyed top-2, 4 rows per thread ----
        float m1[4] = {CUDART_INF_F, CUDART_INF_F, CUDART_INF_F, CUDART_INF_F};
        float m2[4] = {CUDART_INF_F, CUDART_INF_F, CUDART_INF_F, CUDART_INF_F};

        // merge a pair of keys into row rr's top-2 (pure FMNMX, no predicates)
        #define MERGE(rr, k0, k1) {                               \
            const float lo = fminf(k0, k1);                       \
            const float hi = fmaxf(k0, k1);                       \
            const float tx = fmaxf(m1[rr], lo);                   \
            m2[rr] = fminf(fminf(m2[rr], tx), hi);                \
            m1[rr] = fminf(m1[rr], lo); }

        for (int nc = 0; nc < 8; nc++) {          // 8 chunks of 64 codes
            #pragma unroll
            for (int h = 0; h < 2; h++) {         // n-half: nf in [4h, 4h+4)
                float acc[2][4][4];
                #pragma unroll
                for (int t = 0; t < 2; t++)
                    #pragma unroll
                    for (int nfl = 0; nfl < 4; nfl++) {
                        acc[t][nfl][0] = 0.f; acc[t][nfl][1] = 0.f;
                        acc[t][nfl][2] = 0.f; acc[t][nfl][3] = 0.f;
                    }
                #pragma unroll
                for (int ks = 0; ks < 4; ks++) {
                    uint32_t bh[4][2];
                    #pragma unroll
                    for (int pr2 = 0; pr2 < 2; pr2++) {
                        const int row = nc * 64 + (2 * h + pr2) * 16 + browo;
                        const int ch  = 2 * ks + bchs;
                        LDSM4(bh[2 * pr2][0], bh[2 * pr2][1],
                              bh[2 * pr2 + 1][0], bh[2 * pr2 + 1][1],
                              sptr(sm + SM_B0 + swz(row, ch)));
                    }
                    #pragma unroll
                    for (int t = 0; t < 2; t++)
                        #pragma unroll
                        for (int nfl = 0; nfl < 4; nfl++)
                            hmma(acc[t][nfl][0], acc[t][nfl][1],
                                 acc[t][nfl][2], acc[t][nfl][3],
                                 aF[t][ks][0], aF[t][ks][1],
                                 aF[t][ks][2], aF[t][ks][3],
                                 bh[nfl][0], bh[nfl][1]);
                }
                // scores: rank = esq - 2*dot; keys embed the code index
                #pragma unroll
                for (int nfl = 0; nfl < 4; nfl++) {
                    const int col = nc * 64 + (4 * h + nfl) * 8 + 2 * g;
                    const float2 eq = *reinterpret_cast<const float2*>(esq + col);
                    float k0, k1;
                    k0 = mkkey(__fmaf_rn(-2.0f, acc[0][nfl][0], eq.x), col);
                    k1 = mkkey(__fmaf_rn(-2.0f, acc[0][nfl][1], eq.y), col + 1);
                    MERGE(0, k0, k1);
                    k0 = mkkey(__fmaf_rn(-2.0f, acc[0][nfl][2], eq.x), col);
                    k1 = mkkey(__fmaf_rn(-2.0f, acc[0][nfl][3], eq.y), col + 1);
                    MERGE(1, k0, k1);
                    k0 = mkkey(__fmaf_rn(-2.0f, acc[1][nfl][0], eq.x), col);
                    k1 = mkkey(__fmaf_rn(-2.0f, acc[1][nfl][1], eq.y), col + 1);
                    MERGE(2, k0, k1);
                    k0 = mkkey(__fmaf_rn(-2.0f, acc[1][nfl][2], eq.x), col);
                    k1 = mkkey(__fmaf_rn(-2.0f, acc[1][nfl][3], eq.y), col + 1);
                    MERGE(3, k0, k1);
                }
            }
        }
        #undef MERGE

        // ---- quad reduce on keys (pure FMNMX + shuffles); winner or -1 ----
        #pragma unroll
        for (int rr = 0; rr < 4; rr++) {
            #pragma unroll
            for (int d = 1; d <= 2; d <<= 1) {
                const float o1 = __shfl_xor_sync(0xffffffffu, m1[rr], d);
                const float o2 = __shfl_xor_sync(0xffffffffu, m2[rr], d);
                const float tx = fmaxf(m1[rr], o1);
                m2[rr] = fminf(fminf(m2[rr], o2), tx);
                m1[rr] = fminf(m1[rr], o1);
            }
            if (g == 0) {
                const int row = (rr >> 1) * 16 + qr + 8 * (rr & 1);
                scrWin[row] = (m2[rr] - m1[rr] > MARGIN)
                              ? (__float_as_int(m1[rr]) & 0x1FF) : -1;
            }
        }
        __syncwarp();

        // ---- in-warp exact rescue (warp-uniform control flow) ----
        #pragma unroll 1
        for (int r = 0; r < 32; r++) {
            if (scrWin[r] != -1) continue;          // LDS broadcast, uniform
            scrX[lane]      = __ldg(xb + (size_t)lane * VQ_HW + r);
            scrX[lane + 32] = __ldg(xb + (size_t)(lane + 32) * VQ_HW + r);
            __syncwarp();
            float xq = 0.0f;
            #pragma unroll
            for (int c = 0; c < VQ_D; c++)
                xq = __fadd_rn(xq, __fmul_rn(scrX[c], scrX[c]));
            float bd = CUDART_INF_F; int bk = 0x7FFFFFFF;
            #pragma unroll 2
            for (int k = lane; k < VQ_K; k += 32) {
                const float d = exact_dist(scrX, emb, xq, esq[k], k);
                if (d < bd || (d == bd && k < bk)) { bd = d; bk = k; }
            }
            #pragma unroll
            for (int off = 16; off; off >>= 1) {
                const float od = __shfl_xor_sync(0xffffffffu, bd, off);
                const int   oi = __shfl_xor_sync(0xffffffffu, bk, off);
                if (od < bd || (od == bd && oi < bk)) { bd = od; bk = oi; }
            }
            if (lane == 0) scrWin[r] = bk;
            __syncwarp();
        }
        __syncwarp();

        // ---- gather winners + store (float4 along pixel dim), both halves ----
        #pragma unroll
        for (int t = 0; t < 2; t++) {
            #pragma unroll
            for (int it = 0; it < 8; it++) {
                const int c  = it * 8 + (lane >> 2);
                const int p4 = (lane & 3) * 4;
                const int w0 = scrWin[16 * t + p4 + 0], w1 = scrWin[16 * t + p4 + 1];
                const int w2 = scrWin[16 * t + p4 + 2], w3 = scrWin[16 * t + p4 + 3];
                float4 v;
                v.x = __ldg(emb + (size_t)w0 * VQ_D + c);
                v.y = __ldg(emb + (size_t)w1 * VQ_D + c);
                v.z = __ldg(emb + (size_t)w2 * VQ_D + c);
                v.w = __ldg(emb + (size_t)w3 * VQ_D + c);
                *reinterpret_cast<float4*>(ob + (size_t)c * VQ_HW + 16 * t + p4) = v;
            }
        }
    }
}

extern "C" void kernel_launch(void* const* d_in, const int* in_sizes, int n_in,
                              void* d_out, int out_size) {
    (void)in_sizes; (void)n_in; (void)out_size;
    const float* x   = (const float*)d_in[0];
    const float* emb = (const float*)d_in[1];
    float* out = (float*)d_out;

    cudaFuncSetAttribute(vq_hmma_kernel, cudaFuncAttributeMaxDynamicSharedMemorySize,
                         SMEM_TOTAL);

    vq_hmma_kernel<<<GRID, THREADS, SMEM_TOTAL>>>(x, emb, out);
}